// round 3
// baseline (speedup 1.0000x reference)
#include <cuda_runtime.h>

static constexpr int NN   = 100000;
static constexpr int D    = 128;
static constexpr int EMAX = 1600000;
static constexpr int LDS_PAD = 132;   // smem lead dim (words), conflict-free

// Scratch (allocation-free rule: __device__ globals)
__device__ int  g_cnt[NN];
__device__ int  g_off[NN + 1];
__device__ int  g_cur[NN];
__device__ int2 g_edge[EMAX];         // packed (src, float_bits(w)) binned by dst

// ---------------------------------------------------------------------------
__global__ void zero_cnt_kernel() {
    int i = blockIdx.x * blockDim.x + threadIdx.x;
    if (i < NN) g_cnt[i] = 0;
}

__global__ void hist_kernel(const int* __restrict__ dst, int nE) {
    int e = blockIdx.x * blockDim.x + threadIdx.x;
    if (e < nE) atomicAdd(&g_cnt[dst[e]], 1);
}

// Single-CTA prefix scan over g_cnt -> g_off (exclusive) and g_cur (cursor).
__global__ void scan_kernel() {
    __shared__ int part[1024];
    const int CH = (NN + 1023) / 1024;        // 98
    int t  = threadIdx.x;
    int lo = t * CH;
    int hi = min(lo + CH, NN);

    int s = 0;
    for (int i = lo; i < hi; i++) s += g_cnt[i];
    part[t] = s;
    __syncthreads();
    // Hillis-Steele inclusive scan over 1024 partials
    for (int d = 1; d < 1024; d <<= 1) {
        int v = part[t];
        int u = (t >= d) ? part[t - d] : 0;
        __syncthreads();
        part[t] = v + u;
        __syncthreads();
    }
    int run = (t == 0) ? 0 : part[t - 1];
    for (int i = lo; i < hi; i++) {
        int c = g_cnt[i];
        g_off[i] = run;
        g_cur[i] = run;
        run += c;
    }
    if (t == 1023) g_off[NN] = run;
}

__global__ void bin_kernel(const int*   __restrict__ src,
                           const int*   __restrict__ dst,
                           const float* __restrict__ ew,
                           int nE) {
    int e = blockIdx.x * blockDim.x + threadIdx.x;
    if (e >= nE) return;
    int d = dst[e];
    int p = atomicAdd(&g_cur[d], 1);
    g_edge[p] = make_int2(src[e], __float_as_int(ew[e]));
}

// ---------------------------------------------------------------------------
// Fused gather + tf32 GEMM.
// 512 threads = 16 warps. CTA tile: 128 nodes x 128 out-cols, K=128.
// Gather: warp w accumulates nodes [row0 + 8w, row0 + 8w + 8) into registers
//         (fp32), writes tf32 rows into As.
// GEMM:   warps 4(m) x 4(n); warp tile 32x32 = 2 m16 x 4 n8 mma tiles.
// ---------------------------------------------------------------------------
__device__ __forceinline__ unsigned f2tf32(float f) {
    unsigned u;
    asm("cvt.rna.tf32.f32 %0, %1;" : "=r"(u) : "f"(f));
    return u;
}

__device__ __forceinline__ void mma_tf32(float* d, const unsigned* a, const unsigned* b) {
    asm volatile(
        "mma.sync.aligned.m16n8k8.row.col.f32.tf32.tf32.f32 "
        "{%0,%1,%2,%3}, {%4,%5,%6,%7}, {%8,%9}, {%0,%1,%2,%3};"
        : "+f"(d[0]), "+f"(d[1]), "+f"(d[2]), "+f"(d[3])
        : "r"(a[0]), "r"(a[1]), "r"(a[2]), "r"(a[3]),
          "r"(b[0]), "r"(b[1]));
}

__global__ __launch_bounds__(512, 1)
void fused_gather_gemm_kernel(const float* __restrict__ feat,
                              const float* __restrict__ W,
                              const float* __restrict__ b,
                              float*       __restrict__ y) {
    extern __shared__ unsigned sm[];
    unsigned* As = sm;                        // [128][LDS_PAD] tf32 h tile
    unsigned* Bs = sm + D * LDS_PAD;          // [128][LDS_PAD] tf32 W
    float*    bs = reinterpret_cast<float*>(sm + 2 * D * LDS_PAD);

    const int tid  = threadIdx.x;
    const int lane = tid & 31;
    const int wid  = tid >> 5;                // 0..15
    const int row0 = blockIdx.x * 128;

    // ---- Stage B (W, 128x128) as tf32 ----
    #pragma unroll
    for (int it = 0; it < 8; it++) {
        int idx = tid + it * 512;             // float4 index
        int r   = idx >> 5;
        int c4  = (idx & 31) * 4;
        float4 v = *reinterpret_cast<const float4*>(&W[r * D + c4]);
        unsigned* p = &Bs[r * LDS_PAD + c4];
        p[0] = f2tf32(v.x); p[1] = f2tf32(v.y);
        p[2] = f2tf32(v.z); p[3] = f2tf32(v.w);
    }
    if (tid < 128) bs[tid] = b[tid];

    // ---- Gather: warp accumulates 8 node rows ----
    #pragma unroll 1
    for (int v_it = 0; v_it < 8; v_it++) {
        int r = wid * 8 + v_it;               // smem row 0..127
        int v = row0 + r;
        float4 acc = make_float4(0.f, 0.f, 0.f, 0.f);
        if (v < NN) {
            int beg = g_off[v];
            int end = g_off[v + 1];
            for (int j0 = beg; j0 < end; j0 += 32) {
                int n = min(32, end - j0);
                int2 e = (lane < n) ? g_edge[j0 + lane] : make_int2(0, 0);
                int i = 0;
                for (; i + 4 <= n; i += 4) {
                    int   s0 = __shfl_sync(0xffffffffu, e.x, i);
                    int   s1 = __shfl_sync(0xffffffffu, e.x, i + 1);
                    int   s2 = __shfl_sync(0xffffffffu, e.x, i + 2);
                    int   s3 = __shfl_sync(0xffffffffu, e.x, i + 3);
                    float w0 = __int_as_float(__shfl_sync(0xffffffffu, e.y, i));
                    float w1 = __int_as_float(__shfl_sync(0xffffffffu, e.y, i + 1));
                    float w2 = __int_as_float(__shfl_sync(0xffffffffu, e.y, i + 2));
                    float w3 = __int_as_float(__shfl_sync(0xffffffffu, e.y, i + 3));
                    float4 f0 = *reinterpret_cast<const float4*>(feat + (size_t)s0 * D + lane * 4);
                    float4 f1 = *reinterpret_cast<const float4*>(feat + (size_t)s1 * D + lane * 4);
                    float4 f2 = *reinterpret_cast<const float4*>(feat + (size_t)s2 * D + lane * 4);
                    float4 f3 = *reinterpret_cast<const float4*>(feat + (size_t)s3 * D + lane * 4);
                    acc.x = fmaf(w0, f0.x, acc.x); acc.y = fmaf(w0, f0.y, acc.y);
                    acc.z = fmaf(w0, f0.z, acc.z); acc.w = fmaf(w0, f0.w, acc.w);
                    acc.x = fmaf(w1, f1.x, acc.x); acc.y = fmaf(w1, f1.y, acc.y);
                    acc.z = fmaf(w1, f1.z, acc.z); acc.w = fmaf(w1, f1.w, acc.w);
                    acc.x = fmaf(w2, f2.x, acc.x); acc.y = fmaf(w2, f2.y, acc.y);
                    acc.z = fmaf(w2, f2.z, acc.z); acc.w = fmaf(w2, f2.w, acc.w);
                    acc.x = fmaf(w3, f3.x, acc.x); acc.y = fmaf(w3, f3.y, acc.y);
                    acc.z = fmaf(w3, f3.z, acc.z); acc.w = fmaf(w3, f3.w, acc.w);
                }
                for (; i < n; i++) {
                    int   si = __shfl_sync(0xffffffffu, e.x, i);
                    float wi = __int_as_float(__shfl_sync(0xffffffffu, e.y, i));
                    float4 f = *reinterpret_cast<const float4*>(feat + (size_t)si * D + lane * 4);
                    acc.x = fmaf(wi, f.x, acc.x); acc.y = fmaf(wi, f.y, acc.y);
                    acc.z = fmaf(wi, f.z, acc.z); acc.w = fmaf(wi, f.w, acc.w);
                }
            }
        }
        uint4 t;
        t.x = f2tf32(acc.x); t.y = f2tf32(acc.y);
        t.z = f2tf32(acc.z); t.w = f2tf32(acc.w);
        *reinterpret_cast<uint4*>(&As[r * LDS_PAD + lane * 4]) = t;
    }
    __syncthreads();

    // ---- GEMM: 4x4 warps, warp tile 32 rows x 32 cols ----
    const int wm = wid & 3;
    const int wn = wid >> 2;
    const int g  = lane >> 2;
    const int tg = lane & 3;

    float acc[2][4][4];
    #pragma unroll
    for (int mi = 0; mi < 2; mi++)
        #pragma unroll
        for (int ni = 0; ni < 4; ni++)
            #pragma unroll
            for (int c = 0; c < 4; c++) acc[mi][ni][c] = 0.f;

    const unsigned* Abase = &As[(wm * 32 + g) * LDS_PAD + tg];
    const unsigned* Bbase = &Bs[(wn * 32 + g) * LDS_PAD + tg];

    #pragma unroll 4
    for (int kk = 0; kk < 16; kk++) {
        const int k0 = kk * 8;
        unsigned af[2][4];
        #pragma unroll
        for (int mi = 0; mi < 2; mi++) {
            const unsigned* p = Abase + mi * 16 * LDS_PAD + k0;
            af[mi][0] = p[0];
            af[mi][1] = p[8 * LDS_PAD];
            af[mi][2] = p[4];
            af[mi][3] = p[8 * LDS_PAD + 4];
        }
        unsigned bf[4][2];
        #pragma unroll
        for (int ni = 0; ni < 4; ni++) {
            const unsigned* p = Bbase + ni * 8 * LDS_PAD + k0;
            bf[ni][0] = p[0];
            bf[ni][1] = p[4];
        }
        #pragma unroll
        for (int mi = 0; mi < 2; mi++)
            #pragma unroll
            for (int ni = 0; ni < 4; ni++)
                mma_tf32(acc[mi][ni], af[mi], bf[ni]);
    }

    // ---- Epilogue ----
    #pragma unroll
    for (int mi = 0; mi < 2; mi++) {
        #pragma unroll
        for (int ni = 0; ni < 4; ni++) {
            int col = wn * 32 + ni * 8 + 2 * tg;
            float b0 = bs[col], b1 = bs[col + 1];
            int r_lo = row0 + wm * 32 + mi * 16 + g;
            int r_hi = r_lo + 8;
            if (r_lo < NN) {
                float2 o = make_float2(acc[mi][ni][0] + b0, acc[mi][ni][1] + b1);
                *reinterpret_cast<float2*>(&y[(size_t)r_lo * D + col]) = o;
            }
            if (r_hi < NN) {
                float2 o = make_float2(acc[mi][ni][2] + b0, acc[mi][ni][3] + b1);
                *reinterpret_cast<float2*>(&y[(size_t)r_hi * D + col]) = o;
            }
        }
    }
}

// ---------------------------------------------------------------------------
extern "C" void kernel_launch(void* const* d_in, const int* in_sizes, int n_in,
                              void* d_out, int out_size) {
    const float* feat = (const float*)d_in[0];
    const int*   src  = (const int*)  d_in[1];
    const int*   dst  = (const int*)  d_in[2];
    const float* ew   = (const float*)d_in[3];
    const float* W    = (const float*)d_in[4];
    const float* b    = (const float*)d_in[5];
    float*       y    = (float*)d_out;
    int nE = in_sizes[1];

    zero_cnt_kernel<<<(NN + 255) / 256, 256>>>();
    hist_kernel<<<(nE + 255) / 256, 256>>>(dst, nE);
    scan_kernel<<<1, 1024>>>();
    bin_kernel<<<(nE + 255) / 256, 256>>>(src, dst, ew, nE);

    int smem = (2 * D * LDS_PAD + D) * (int)sizeof(float);   // ~135.7KB
    cudaFuncSetAttribute(fused_gather_gemm_kernel,
                         cudaFuncAttributeMaxDynamicSharedMemorySize, smem);
    fused_gather_gemm_kernel<<<(NN + 127) / 128, 512, smem>>>(feat, W, b, y);
}

// round 6
// speedup vs baseline: 1.1352x; 1.1352x over previous
#include <cuda_runtime.h>

static constexpr int NN   = 100000;
static constexpr int D    = 128;
static constexpr int EMAX = 1600000;
static constexpr int LDS_PAD = 132;   // smem lead dim (words), conflict-free

// Scratch (allocation-free rule: __device__ globals)
__device__ float g_h[(size_t)NN * D];
__device__ int   g_cnt[NN];
__device__ int   g_off[NN + 1];
__device__ int   g_cur[NN];
__device__ int2  g_edge[EMAX];        // (src, float_bits(w)) binned by dst

// ---------------------------------------------------------------------------
__global__ void zero_cnt_kernel() {
    int i = blockIdx.x * blockDim.x + threadIdx.x;
    if (i < NN) g_cnt[i] = 0;
}

__global__ void hist_kernel(const int* __restrict__ dst, int nE) {
    int e = blockIdx.x * blockDim.x + threadIdx.x;
    if (e < nE) {
        int d = dst[e];
        if (d >= 0 && d < NN) atomicAdd(&g_cnt[d], 1);
    }
}

// Single-CTA prefix scan over g_cnt -> g_off (exclusive) and g_cur (cursor).
__global__ void scan_kernel() {
    __shared__ int part[1024];
    const int CH = (NN + 1023) / 1024;        // 98
    int t  = threadIdx.x;
    int lo = t * CH;
    int hi = min(lo + CH, NN);

    int s = 0;
    for (int i = lo; i < hi; i++) s += g_cnt[i];
    part[t] = s;
    __syncthreads();
    for (int d = 1; d < 1024; d <<= 1) {
        int v = part[t];
        int u = (t >= d) ? part[t - d] : 0;
        __syncthreads();
        part[t] = v + u;
        __syncthreads();
    }
    int run = (t == 0) ? 0 : part[t - 1];
    for (int i = lo; i < hi; i++) {
        int c = g_cnt[i];
        g_off[i] = run;
        g_cur[i] = run;
        run += c;
    }
    if (t == 1023) g_off[NN] = run;
}

__global__ void bin_kernel(const int*   __restrict__ src,
                           const int*   __restrict__ dst,
                           const float* __restrict__ ew,
                           int nE) {
    int e = blockIdx.x * blockDim.x + threadIdx.x;
    if (e >= nE) return;
    int d = dst[e];
    if (d < 0 || d >= NN) return;
    int p = atomicAdd(&g_cur[d], 1);
    if (p >= 0 && p < EMAX)
        g_edge[p] = make_int2(src[e], __float_as_int(ew[e]));
}

// ---------------------------------------------------------------------------
// Gather: one warp per node, lane owns cols [lane*4, lane*4+4).
// Edge records are warp-uniform broadcast loads; 8 feature rows in flight.
// ---------------------------------------------------------------------------
__global__ __launch_bounds__(256)
void gather_kernel(const float* __restrict__ feat) {
    int node = (blockIdx.x * blockDim.x + threadIdx.x) >> 5;
    int lane = threadIdx.x & 31;
    if (node >= NN) return;

    int beg = g_off[node];
    int end = g_off[node + 1];

    float4 acc = make_float4(0.f, 0.f, 0.f, 0.f);
    int j = beg;

    for (; j + 8 <= end; j += 8) {
        int2 e[8];
        #pragma unroll
        for (int i = 0; i < 8; i++) e[i] = __ldg(&g_edge[j + i]);
        float4 f[8];
        #pragma unroll
        for (int i = 0; i < 8; i++)
            f[i] = *reinterpret_cast<const float4*>(feat + (size_t)e[i].x * D + lane * 4);
        #pragma unroll
        for (int i = 0; i < 8; i++) {
            float w = __int_as_float(e[i].y);
            acc.x = fmaf(w, f[i].x, acc.x);
            acc.y = fmaf(w, f[i].y, acc.y);
            acc.z = fmaf(w, f[i].z, acc.z);
            acc.w = fmaf(w, f[i].w, acc.w);
        }
    }
    for (; j < end; j++) {
        int2  e = __ldg(&g_edge[j]);
        float w = __int_as_float(e.y);
        float4 f = *reinterpret_cast<const float4*>(feat + (size_t)e.x * D + lane * 4);
        acc.x = fmaf(w, f.x, acc.x); acc.y = fmaf(w, f.y, acc.y);
        acc.z = fmaf(w, f.z, acc.z); acc.w = fmaf(w, f.w, acc.w);
    }

    *reinterpret_cast<float4*>(&g_h[(size_t)node * D + lane * 4]) = acc;
}

// ---------------------------------------------------------------------------
// tf32 GEMM: y = g_h @ W^T + b  (proven R2 kernel)
// ---------------------------------------------------------------------------
__device__ __forceinline__ unsigned f2tf32(float f) {
    unsigned u;
    asm("cvt.rna.tf32.f32 %0, %1;" : "=r"(u) : "f"(f));
    return u;
}

__device__ __forceinline__ void mma_tf32(float* d, const unsigned* a, const unsigned* b) {
    asm volatile(
        "mma.sync.aligned.m16n8k8.row.col.f32.tf32.tf32.f32 "
        "{%0,%1,%2,%3}, {%4,%5,%6,%7}, {%8,%9}, {%0,%1,%2,%3};"
        : "+f"(d[0]), "+f"(d[1]), "+f"(d[2]), "+f"(d[3])
        : "r"(a[0]), "r"(a[1]), "r"(a[2]), "r"(a[3]),
          "r"(b[0]), "r"(b[1]));
}

__global__ void gemm_tf32_kernel(const float* __restrict__ W,
                                 const float* __restrict__ b,
                                 float*       __restrict__ y) {
    extern __shared__ unsigned sm[];
    unsigned* As = sm;                       // [128][LDS_PAD]
    unsigned* Bs = sm + D * LDS_PAD;         // [128][LDS_PAD]
    float*    bs = reinterpret_cast<float*>(sm + 2 * D * LDS_PAD);

    const int tid  = threadIdx.x;
    const int lane = tid & 31;
    const int wid  = tid >> 5;
    const int wm   = wid & 3;
    const int wn   = wid >> 2;
    const int g    = lane >> 2;
    const int tg   = lane & 3;

    const int row0 = blockIdx.x * 128;

    #pragma unroll
    for (int it = 0; it < 16; it++) {
        int idx = tid + it * 256;
        int r   = idx >> 5;
        int c4  = (idx & 31) * 4;
        int row = row0 + r;
        float4 v = (row < NN)
            ? *reinterpret_cast<const float4*>(&g_h[(size_t)row * D + c4])
            : make_float4(0.f, 0.f, 0.f, 0.f);
        unsigned* p = &As[r * LDS_PAD + c4];
        p[0] = f2tf32(v.x); p[1] = f2tf32(v.y);
        p[2] = f2tf32(v.z); p[3] = f2tf32(v.w);
    }
    #pragma unroll
    for (int it = 0; it < 16; it++) {
        int idx = tid + it * 256;
        int r   = idx >> 5;
        int c4  = (idx & 31) * 4;
        float4 v = *reinterpret_cast<const float4*>(&W[r * D + c4]);
        unsigned* p = &Bs[r * LDS_PAD + c4];
        p[0] = f2tf32(v.x); p[1] = f2tf32(v.y);
        p[2] = f2tf32(v.z); p[3] = f2tf32(v.w);
    }
    if (tid < 128) bs[tid] = b[tid];
    __syncthreads();

    float acc[2][8][4];
    #pragma unroll
    for (int mi = 0; mi < 2; mi++)
        #pragma unroll
        for (int ni = 0; ni < 8; ni++)
            #pragma unroll
            for (int c = 0; c < 4; c++) acc[mi][ni][c] = 0.f;

    const unsigned* Abase = &As[(wm * 32 + g) * LDS_PAD + tg];
    const unsigned* Bbase = &Bs[(wn * 64 + g) * LDS_PAD + tg];

    #pragma unroll 4
    for (int kk = 0; kk < 16; kk++) {
        const int k0 = kk * 8;
        unsigned af[2][4];
        #pragma unroll
        for (int mi = 0; mi < 2; mi++) {
            const unsigned* p = Abase + mi * 16 * LDS_PAD + k0;
            af[mi][0] = p[0];
            af[mi][1] = p[8 * LDS_PAD];
            af[mi][2] = p[4];
            af[mi][3] = p[8 * LDS_PAD + 4];
        }
        unsigned bf[8][2];
        #pragma unroll
        for (int ni = 0; ni < 8; ni++) {
            const unsigned* p = Bbase + ni * 8 * LDS_PAD + k0;
            bf[ni][0] = p[0];
            bf[ni][1] = p[4];
        }
        #pragma unroll
        for (int mi = 0; mi < 2; mi++)
            #pragma unroll
            for (int ni = 0; ni < 8; ni++)
                mma_tf32(acc[mi][ni], af[mi], bf[ni]);
    }

    #pragma unroll
    for (int mi = 0; mi < 2; mi++) {
        #pragma unroll
        for (int ni = 0; ni < 8; ni++) {
            int col = wn * 64 + ni * 8 + 2 * tg;
            float b0 = bs[col], b1 = bs[col + 1];
            int r_lo = row0 + wm * 32 + mi * 16 + g;
            int r_hi = r_lo + 8;
            if (r_lo < NN) {
                float2 o = make_float2(acc[mi][ni][0] + b0, acc[mi][ni][1] + b1);
                *reinterpret_cast<float2*>(&y[(size_t)r_lo * D + col]) = o;
            }
            if (r_hi < NN) {
                float2 o = make_float2(acc[mi][ni][2] + b0, acc[mi][ni][3] + b1);
                *reinterpret_cast<float2*>(&y[(size_t)r_hi * D + col]) = o;
            }
        }
    }
}

// ---------------------------------------------------------------------------
extern "C" void kernel_launch(void* const* d_in, const int* in_sizes, int n_in,
                              void* d_out, int out_size) {
    const float* feat = (const float*)d_in[0];
    const int*   src  = (const int*)  d_in[1];
    const int*   dst  = (const int*)  d_in[2];
    const float* ew   = (const float*)d_in[3];
    const float* W    = (const float*)d_in[4];
    const float* b    = (const float*)d_in[5];
    float*       y    = (float*)d_out;
    int nE = in_sizes[1];
    if (nE > EMAX) nE = EMAX;

    zero_cnt_kernel<<<(NN + 255) / 256, 256>>>();
    hist_kernel<<<(nE + 255) / 256, 256>>>(dst, nE);
    scan_kernel<<<1, 1024>>>();
    bin_kernel<<<(nE + 255) / 256, 256>>>(src, dst, ew, nE);

    // gather: one warp per node
    {
        long long total = (long long)NN * 32;
        gather_kernel<<<(int)((total + 255) / 256), 256>>>(feat);
    }

    // tf32 GEMM
    {
        int smem = (2 * D * LDS_PAD + D) * (int)sizeof(float);
        cudaFuncSetAttribute(gemm_tf32_kernel,
                             cudaFuncAttributeMaxDynamicSharedMemorySize, smem);
        gemm_tf32_kernel<<<(NN + 127) / 128, 256, smem>>>(W, b, y);
    }
}

// round 7
// speedup vs baseline: 1.1466x; 1.0100x over previous
#include <cuda_runtime.h>
#include <cuda_fp16.h>

static constexpr int NN   = 100000;
static constexpr int D    = 128;
static constexpr int EMAX = 1600000;
static constexpr int LDS_PAD = 132;   // smem lead dim (words), conflict-free

// Scratch (allocation-free rule: __device__ globals)
__device__ float g_h[(size_t)NN * D];
__device__ uint2 g_feat16[(size_t)NN * 32];   // fp16 feature: 32 x uint2 (8B) per row
__device__ int   g_cnt[NN];
__device__ int   g_off[NN + 1];
__device__ int   g_cur[NN];
__device__ int2  g_edge[EMAX];                // (src, float_bits(w)) binned by dst

// ---------------------------------------------------------------------------
__global__ void zero_cnt_kernel() {
    int i = blockIdx.x * blockDim.x + threadIdx.x;
    if (i < NN) g_cnt[i] = 0;
}

// feature fp32 -> fp16 (4 floats -> 1 uint2 per thread)
__global__ void conv_kernel(const float* __restrict__ feat) {
    int i = blockIdx.x * blockDim.x + threadIdx.x;   // uint2 index
    if (i < NN * 32) {
        float4 v = *reinterpret_cast<const float4*>(feat + (size_t)i * 4);
        __half2 h0 = __floats2half2_rn(v.x, v.y);
        __half2 h1 = __floats2half2_rn(v.z, v.w);
        g_feat16[i] = make_uint2(*reinterpret_cast<unsigned*>(&h0),
                                 *reinterpret_cast<unsigned*>(&h1));
    }
}

__global__ void hist_kernel(const int* __restrict__ dst, int nE) {
    int e = blockIdx.x * blockDim.x + threadIdx.x;
    if (e < nE) {
        int d = dst[e];
        if (d >= 0 && d < NN) atomicAdd(&g_cnt[d], 1);
    }
}

// Single-CTA prefix scan over g_cnt -> g_off (exclusive) and g_cur (cursor).
__global__ void scan_kernel() {
    __shared__ int part[1024];
    const int CH = (NN + 1023) / 1024;        // 98
    int t  = threadIdx.x;
    int lo = t * CH;
    int hi = min(lo + CH, NN);

    int s = 0;
    for (int i = lo; i < hi; i++) s += g_cnt[i];
    part[t] = s;
    __syncthreads();
    for (int d = 1; d < 1024; d <<= 1) {
        int v = part[t];
        int u = (t >= d) ? part[t - d] : 0;
        __syncthreads();
        part[t] = v + u;
        __syncthreads();
    }
    int run = (t == 0) ? 0 : part[t - 1];
    for (int i = lo; i < hi; i++) {
        int c = g_cnt[i];
        g_off[i] = run;
        g_cur[i] = run;
        run += c;
    }
    if (t == 1023) g_off[NN] = run;
}

__global__ void bin_kernel(const int*   __restrict__ src,
                           const int*   __restrict__ dst,
                           const float* __restrict__ ew,
                           int nE) {
    int e = blockIdx.x * blockDim.x + threadIdx.x;
    if (e >= nE) return;
    int d = dst[e];
    if (d < 0 || d >= NN) return;
    int p = atomicAdd(&g_cur[d], 1);
    if (p >= 0 && p < EMAX)
        g_edge[p] = make_int2(src[e], __float_as_int(ew[e]));
}

// ---------------------------------------------------------------------------
// Gather (fp16 features): one warp per node.
// Lane owns cols [lane*4, lane*4+4): reads one uint2 (4 halves) per edge row.
// 8 feature rows (256B each) in flight per warp; fp32 accumulation.
// ---------------------------------------------------------------------------
__global__ __launch_bounds__(256)
void gather_kernel() {
    int node = (blockIdx.x * blockDim.x + threadIdx.x) >> 5;
    int lane = threadIdx.x & 31;
    if (node >= NN) return;

    int beg = g_off[node];
    int end = g_off[node + 1];

    float4 acc = make_float4(0.f, 0.f, 0.f, 0.f);
    int j = beg;

    for (; j + 8 <= end; j += 8) {
        int2 e[8];
        #pragma unroll
        for (int i = 0; i < 8; i++) e[i] = __ldg(&g_edge[j + i]);
        uint2 f[8];
        #pragma unroll
        for (int i = 0; i < 8; i++)
            f[i] = __ldg(&g_feat16[(size_t)e[i].x * 32 + lane]);
        #pragma unroll
        for (int i = 0; i < 8; i++) {
            float w = __int_as_float(e[i].y);
            float2 a = __half22float2(*reinterpret_cast<__half2*>(&f[i].x));
            float2 b = __half22float2(*reinterpret_cast<__half2*>(&f[i].y));
            acc.x = fmaf(w, a.x, acc.x);
            acc.y = fmaf(w, a.y, acc.y);
            acc.z = fmaf(w, b.x, acc.z);
            acc.w = fmaf(w, b.y, acc.w);
        }
    }
    for (; j < end; j++) {
        int2  e = __ldg(&g_edge[j]);
        float w = __int_as_float(e.y);
        uint2 f = __ldg(&g_feat16[(size_t)e.x * 32 + lane]);
        float2 a = __half22float2(*reinterpret_cast<__half2*>(&f.x));
        float2 b = __half22float2(*reinterpret_cast<__half2*>(&f.y));
        acc.x = fmaf(w, a.x, acc.x);
        acc.y = fmaf(w, a.y, acc.y);
        acc.z = fmaf(w, b.x, acc.z);
        acc.w = fmaf(w, b.y, acc.w);
    }

    *reinterpret_cast<float4*>(&g_h[(size_t)node * D + lane * 4]) = acc;
}

// ---------------------------------------------------------------------------
// tf32 GEMM: y = g_h @ W^T + b  (proven R2 kernel)
// ---------------------------------------------------------------------------
__device__ __forceinline__ unsigned f2tf32(float f) {
    unsigned u;
    asm("cvt.rna.tf32.f32 %0, %1;" : "=r"(u) : "f"(f));
    return u;
}

__device__ __forceinline__ void mma_tf32(float* d, const unsigned* a, const unsigned* b) {
    asm volatile(
        "mma.sync.aligned.m16n8k8.row.col.f32.tf32.tf32.f32 "
        "{%0,%1,%2,%3}, {%4,%5,%6,%7}, {%8,%9}, {%0,%1,%2,%3};"
        : "+f"(d[0]), "+f"(d[1]), "+f"(d[2]), "+f"(d[3])
        : "r"(a[0]), "r"(a[1]), "r"(a[2]), "r"(a[3]),
          "r"(b[0]), "r"(b[1]));
}

__global__ void gemm_tf32_kernel(const float* __restrict__ W,
                                 const float* __restrict__ b,
                                 float*       __restrict__ y) {
    extern __shared__ unsigned sm[];
    unsigned* As = sm;                       // [128][LDS_PAD]
    unsigned* Bs = sm + D * LDS_PAD;         // [128][LDS_PAD]
    float*    bs = reinterpret_cast<float*>(sm + 2 * D * LDS_PAD);

    const int tid  = threadIdx.x;
    const int lane = tid & 31;
    const int wid  = tid >> 5;
    const int wm   = wid & 3;
    const int wn   = wid >> 2;
    const int g    = lane >> 2;
    const int tg   = lane & 3;

    const int row0 = blockIdx.x * 128;

    #pragma unroll
    for (int it = 0; it < 16; it++) {
        int idx = tid + it * 256;
        int r   = idx >> 5;
        int c4  = (idx & 31) * 4;
        int row = row0 + r;
        float4 v = (row < NN)
            ? *reinterpret_cast<const float4*>(&g_h[(size_t)row * D + c4])
            : make_float4(0.f, 0.f, 0.f, 0.f);
        unsigned* p = &As[r * LDS_PAD + c4];
        p[0] = f2tf32(v.x); p[1] = f2tf32(v.y);
        p[2] = f2tf32(v.z); p[3] = f2tf32(v.w);
    }
    #pragma unroll
    for (int it = 0; it < 16; it++) {
        int idx = tid + it * 256;
        int r   = idx >> 5;
        int c4  = (idx & 31) * 4;
        float4 v = *reinterpret_cast<const float4*>(&W[r * D + c4]);
        unsigned* p = &Bs[r * LDS_PAD + c4];
        p[0] = f2tf32(v.x); p[1] = f2tf32(v.y);
        p[2] = f2tf32(v.z); p[3] = f2tf32(v.w);
    }
    if (tid < 128) bs[tid] = b[tid];
    __syncthreads();

    float acc[2][8][4];
    #pragma unroll
    for (int mi = 0; mi < 2; mi++)
        #pragma unroll
        for (int ni = 0; ni < 8; ni++)
            #pragma unroll
            for (int c = 0; c < 4; c++) acc[mi][ni][c] = 0.f;

    const unsigned* Abase = &As[(wm * 32 + g) * LDS_PAD + tg];
    const unsigned* Bbase = &Bs[(wn * 64 + g) * LDS_PAD + tg];

    #pragma unroll 4
    for (int kk = 0; kk < 16; kk++) {
        const int k0 = kk * 8;
        unsigned af[2][4];
        #pragma unroll
        for (int mi = 0; mi < 2; mi++) {
            const unsigned* p = Abase + mi * 16 * LDS_PAD + k0;
            af[mi][0] = p[0];
            af[mi][1] = p[8 * LDS_PAD];
            af[mi][2] = p[4];
            af[mi][3] = p[8 * LDS_PAD + 4];
        }
        unsigned bf[8][2];
        #pragma unroll
        for (int ni = 0; ni < 8; ni++) {
            const unsigned* p = Bbase + ni * 8 * LDS_PAD + k0;
            bf[ni][0] = p[0];
            bf[ni][1] = p[4];
        }
        #pragma unroll
        for (int mi = 0; mi < 2; mi++)
            #pragma unroll
            for (int ni = 0; ni < 8; ni++)
                mma_tf32(acc[mi][ni], af[mi], bf[ni]);
    }

    #pragma unroll
    for (int mi = 0; mi < 2; mi++) {
        #pragma unroll
        for (int ni = 0; ni < 8; ni++) {
            int col = wn * 64 + ni * 8 + 2 * tg;
            float b0 = bs[col], b1 = bs[col + 1];
            int r_lo = row0 + wm * 32 + mi * 16 + g;
            int r_hi = r_lo + 8;
            if (r_lo < NN) {
                float2 o = make_float2(acc[mi][ni][0] + b0, acc[mi][ni][1] + b1);
                *reinterpret_cast<float2*>(&y[(size_t)r_lo * D + col]) = o;
            }
            if (r_hi < NN) {
                float2 o = make_float2(acc[mi][ni][2] + b0, acc[mi][ni][3] + b1);
                *reinterpret_cast<float2*>(&y[(size_t)r_hi * D + col]) = o;
            }
        }
    }
}

// ---------------------------------------------------------------------------
extern "C" void kernel_launch(void* const* d_in, const int* in_sizes, int n_in,
                              void* d_out, int out_size) {
    const float* feat = (const float*)d_in[0];
    const int*   src  = (const int*)  d_in[1];
    const int*   dst  = (const int*)  d_in[2];
    const float* ew   = (const float*)d_in[3];
    const float* W    = (const float*)d_in[4];
    const float* b    = (const float*)d_in[5];
    float*       y    = (float*)d_out;
    int nE = in_sizes[1];
    if (nE > EMAX) nE = EMAX;

    zero_cnt_kernel<<<(NN + 255) / 256, 256>>>();
    conv_kernel<<<(NN * 32 + 255) / 256, 256>>>(feat);
    hist_kernel<<<(nE + 255) / 256, 256>>>(dst, nE);
    scan_kernel<<<1, 1024>>>();
    bin_kernel<<<(nE + 255) / 256, 256>>>(src, dst, ew, nE);

    // gather: one warp per node (fp16 feature reads)
    {
        long long total = (long long)NN * 32;
        gather_kernel<<<(int)((total + 255) / 256), 256>>>();
    }

    // tf32 GEMM
    {
        int smem = (2 * D * LDS_PAD + D) * (int)sizeof(float);
        cudaFuncSetAttribute(gemm_tf32_kernel,
                             cudaFuncAttributeMaxDynamicSharedMemorySize, smem);
        gemm_tf32_kernel<<<(NN + 127) / 128, 256, smem>>>(W, b, y);
    }
}

// round 9
// speedup vs baseline: 2.3560x; 2.0548x over previous
#include <cuda_runtime.h>
#include <cuda_fp16.h>

static constexpr int NN   = 100000;
static constexpr int D    = 128;
static constexpr int EMAX = 1600000;
static constexpr int LDS_PAD = 132;   // smem lead dim (words), conflict-free
static constexpr int SCAN_B  = 1024;
static constexpr int SCAN_NB = (NN + SCAN_B - 1) / SCAN_B;   // 98

// Scratch (allocation-free rule: __device__ globals)
__device__ float g_h[(size_t)NN * D];
__device__ uint2 g_feat16[(size_t)NN * 32];   // fp16 feature: 32 x uint2 per row
__device__ int   g_cnt[NN];
__device__ int   g_off[NN + 1];
__device__ int   g_cur[NN];
__device__ int   g_bsum[128];
__device__ int   g_bpre[128];
__device__ int2  g_edge[EMAX];                // (src, float_bits(w)) binned by dst

// ---------------------------------------------------------------------------
__global__ void zero_cnt_kernel() {
    int i = blockIdx.x * blockDim.x + threadIdx.x;
    if (i < NN) g_cnt[i] = 0;
}

// feature fp32 -> fp16 (4 floats -> 1 uint2 per thread)
__global__ void conv_kernel(const float* __restrict__ feat) {
    int i = blockIdx.x * blockDim.x + threadIdx.x;   // uint2 index
    if (i < NN * 32) {
        float4 v = *reinterpret_cast<const float4*>(feat + (size_t)i * 4);
        __half2 h0 = __floats2half2_rn(v.x, v.y);
        __half2 h1 = __floats2half2_rn(v.z, v.w);
        g_feat16[i] = make_uint2(*reinterpret_cast<unsigned*>(&h0),
                                 *reinterpret_cast<unsigned*>(&h1));
    }
}

__global__ void hist_kernel(const int* __restrict__ dst, int nE) {
    int e = blockIdx.x * blockDim.x + threadIdx.x;
    if (e < nE) {
        int d = dst[e];
        if (d >= 0 && d < NN) atomicAdd(&g_cnt[d], 1);
    }
}

// ---------------------------------------------------------------------------
// 3-phase parallel exclusive scan of g_cnt -> g_off / g_cur
// ---------------------------------------------------------------------------
__global__ __launch_bounds__(SCAN_B)
void scan_block_kernel() {
    __shared__ int sh[SCAN_B];
    const int tid = threadIdx.x;
    const int i   = blockIdx.x * SCAN_B + tid;
    const int v   = (i < NN) ? g_cnt[i] : 0;
    sh[tid] = v;
    __syncthreads();
    #pragma unroll
    for (int d = 1; d < SCAN_B; d <<= 1) {
        int t = sh[tid];
        int u = (tid >= d) ? sh[tid - d] : 0;
        __syncthreads();
        sh[tid] = t + u;
        __syncthreads();
    }
    int incl = sh[tid];
    if (i < NN) g_off[i] = incl - v;              // exclusive within block
    if (tid == SCAN_B - 1) g_bsum[blockIdx.x] = incl;
}

__global__ __launch_bounds__(128)
void scan_tops_kernel() {
    __shared__ int sh[128];
    const int t = threadIdx.x;
    const int v = (t < SCAN_NB) ? g_bsum[t] : 0;
    sh[t] = v;
    __syncthreads();
    #pragma unroll
    for (int d = 1; d < 128; d <<= 1) {
        int a = sh[t];
        int u = (t >= d) ? sh[t - d] : 0;
        __syncthreads();
        sh[t] = a + u;
        __syncthreads();
    }
    if (t < SCAN_NB) g_bpre[t] = sh[t] - v;       // exclusive block prefix
    if (t == 127) g_off[NN] = sh[127];            // grand total
}

__global__ __launch_bounds__(SCAN_B)
void scan_add_kernel() {
    int i = blockIdx.x * SCAN_B + threadIdx.x;
    if (i < NN) {
        int off = g_off[i] + g_bpre[blockIdx.x];
        g_off[i] = off;
        g_cur[i] = off;
    }
}

// ---------------------------------------------------------------------------
__global__ void bin_kernel(const int*   __restrict__ src,
                           const int*   __restrict__ dst,
                           const float* __restrict__ ew,
                           int nE) {
    int e = blockIdx.x * blockDim.x + threadIdx.x;
    if (e >= nE) return;
    int d = dst[e];
    if (d < 0 || d >= NN) return;
    int p = atomicAdd(&g_cur[d], 1);
    if (p >= 0 && p < EMAX)
        g_edge[p] = make_int2(src[e], __float_as_int(ew[e]));
}

// ---------------------------------------------------------------------------
// Gather (fp16 features): one warp per node.
// Lane owns cols [lane*4, lane*4+4): one uint2 (4 halves) per edge row.
// 8 rows in flight; fp32 accumulation.
// ---------------------------------------------------------------------------
__global__ __launch_bounds__(256)
void gather_kernel() {
    int node = (blockIdx.x * blockDim.x + threadIdx.x) >> 5;
    int lane = threadIdx.x & 31;
    if (node >= NN) return;

    int beg = g_off[node];
    int end = g_off[node + 1];

    float4 acc = make_float4(0.f, 0.f, 0.f, 0.f);
    int j = beg;

    for (; j + 8 <= end; j += 8) {
        int2 e[8];
        #pragma unroll
        for (int i = 0; i < 8; i++) e[i] = __ldg(&g_edge[j + i]);
        uint2 f[8];
        #pragma unroll
        for (int i = 0; i < 8; i++)
            f[i] = __ldg(&g_feat16[(size_t)e[i].x * 32 + lane]);
        #pragma unroll
        for (int i = 0; i < 8; i++) {
            float w = __int_as_float(e[i].y);
            float2 a = __half22float2(*reinterpret_cast<__half2*>(&f[i].x));
            float2 b = __half22float2(*reinterpret_cast<__half2*>(&f[i].y));
            acc.x = fmaf(w, a.x, acc.x);
            acc.y = fmaf(w, a.y, acc.y);
            acc.z = fmaf(w, b.x, acc.z);
            acc.w = fmaf(w, b.y, acc.w);
        }
    }
    for (; j < end; j++) {
        int2  e = __ldg(&g_edge[j]);
        float w = __int_as_float(e.y);
        uint2 f = __ldg(&g_feat16[(size_t)e.x * 32 + lane]);
        float2 a = __half22float2(*reinterpret_cast<__half2*>(&f.x));
        float2 b = __half22float2(*reinterpret_cast<__half2*>(&f.y));
        acc.x = fmaf(w, a.x, acc.x);
        acc.y = fmaf(w, a.y, acc.y);
        acc.z = fmaf(w, b.x, acc.z);
        acc.w = fmaf(w, b.y, acc.w);
    }

    *reinterpret_cast<float4*>(&g_h[(size_t)node * D + lane * 4]) = acc;
}

// ---------------------------------------------------------------------------
// tf32 GEMM: y = g_h @ W^T + b
// ---------------------------------------------------------------------------
__device__ __forceinline__ unsigned f2tf32(float f) {
    unsigned u;
    asm("cvt.rna.tf32.f32 %0, %1;" : "=r"(u) : "f"(f));
    return u;
}

__device__ __forceinline__ void mma_tf32(float* d, const unsigned* a, const unsigned* b) {
    asm volatile(
        "mma.sync.aligned.m16n8k8.row.col.f32.tf32.tf32.f32 "
        "{%0,%1,%2,%3}, {%4,%5,%6,%7}, {%8,%9}, {%0,%1,%2,%3};"
        : "+f"(d[0]), "+f"(d[1]), "+f"(d[2]), "+f"(d[3])
        : "r"(a[0]), "r"(a[1]), "r"(a[2]), "r"(a[3]),
          "r"(b[0]), "r"(b[1]));
}

__global__ void gemm_tf32_kernel(const float* __restrict__ W,
                                 const float* __restrict__ b,
                                 float*       __restrict__ y) {
    extern __shared__ unsigned sm[];
    unsigned* As = sm;                       // [128][LDS_PAD]
    unsigned* Bs = sm + D * LDS_PAD;         // [128][LDS_PAD]
    float*    bs = reinterpret_cast<float*>(sm + 2 * D * LDS_PAD);

    const int tid  = threadIdx.x;
    const int lane = tid & 31;
    const int wid  = tid >> 5;
    const int wm   = wid & 3;
    const int wn   = wid >> 2;
    const int g    = lane >> 2;
    const int tg   = lane & 3;

    const int row0 = blockIdx.x * 128;

    #pragma unroll
    for (int it = 0; it < 16; it++) {
        int idx = tid + it * 256;
        int r   = idx >> 5;
        int c4  = (idx & 31) * 4;
        int row = row0 + r;
        float4 v = (row < NN)
            ? *reinterpret_cast<const float4*>(&g_h[(size_t)row * D + c4])
            : make_float4(0.f, 0.f, 0.f, 0.f);
        unsigned* p = &As[r * LDS_PAD + c4];
        p[0] = f2tf32(v.x); p[1] = f2tf32(v.y);
        p[2] = f2tf32(v.z); p[3] = f2tf32(v.w);
    }
    #pragma unroll
    for (int it = 0; it < 16; it++) {
        int idx = tid + it * 256;
        int r   = idx >> 5;
        int c4  = (idx & 31) * 4;
        float4 v = *reinterpret_cast<const float4*>(&W[r * D + c4]);
        unsigned* p = &Bs[r * LDS_PAD + c4];
        p[0] = f2tf32(v.x); p[1] = f2tf32(v.y);
        p[2] = f2tf32(v.z); p[3] = f2tf32(v.w);
    }
    if (tid < 128) bs[tid] = b[tid];
    __syncthreads();

    float acc[2][8][4];
    #pragma unroll
    for (int mi = 0; mi < 2; mi++)
        #pragma unroll
        for (int ni = 0; ni < 8; ni++)
            #pragma unroll
            for (int c = 0; c < 4; c++) acc[mi][ni][c] = 0.f;

    const unsigned* Abase = &As[(wm * 32 + g) * LDS_PAD + tg];
    const unsigned* Bbase = &Bs[(wn * 64 + g) * LDS_PAD + tg];

    #pragma unroll 4
    for (int kk = 0; kk < 16; kk++) {
        const int k0 = kk * 8;
        unsigned af[2][4];
        #pragma unroll
        for (int mi = 0; mi < 2; mi++) {
            const unsigned* p = Abase + mi * 16 * LDS_PAD + k0;
            af[mi][0] = p[0];
            af[mi][1] = p[8 * LDS_PAD];
            af[mi][2] = p[4];
            af[mi][3] = p[8 * LDS_PAD + 4];
        }
        unsigned bf[8][2];
        #pragma unroll
        for (int ni = 0; ni < 8; ni++) {
            const unsigned* p = Bbase + ni * 8 * LDS_PAD + k0;
            bf[ni][0] = p[0];
            bf[ni][1] = p[4];
        }
        #pragma unroll
        for (int mi = 0; mi < 2; mi++)
            #pragma unroll
            for (int ni = 0; ni < 8; ni++)
                mma_tf32(acc[mi][ni], af[mi], bf[ni]);
    }

    #pragma unroll
    for (int mi = 0; mi < 2; mi++) {
        #pragma unroll
        for (int ni = 0; ni < 8; ni++) {
            int col = wn * 64 + ni * 8 + 2 * tg;
            float b0 = bs[col], b1 = bs[col + 1];
            int r_lo = row0 + wm * 32 + mi * 16 + g;
            int r_hi = r_lo + 8;
            if (r_lo < NN) {
                float2 o = make_float2(acc[mi][ni][0] + b0, acc[mi][ni][1] + b1);
                *reinterpret_cast<float2*>(&y[(size_t)r_lo * D + col]) = o;
            }
            if (r_hi < NN) {
                float2 o = make_float2(acc[mi][ni][2] + b0, acc[mi][ni][3] + b1);
                *reinterpret_cast<float2*>(&y[(size_t)r_hi * D + col]) = o;
            }
        }
    }
}

// ---------------------------------------------------------------------------
extern "C" void kernel_launch(void* const* d_in, const int* in_sizes, int n_in,
                              void* d_out, int out_size) {
    const float* feat = (const float*)d_in[0];
    const int*   src  = (const int*)  d_in[1];
    const int*   dst  = (const int*)  d_in[2];
    const float* ew   = (const float*)d_in[3];
    const float* W    = (const float*)d_in[4];
    const float* b    = (const float*)d_in[5];
    float*       y    = (float*)d_out;
    int nE = in_sizes[1];
    if (nE > EMAX) nE = EMAX;
    const int EB = (nE + 255) / 256;

    zero_cnt_kernel<<<(NN + 255) / 256, 256>>>();
    conv_kernel<<<(NN * 32 + 255) / 256, 256>>>(feat);
    hist_kernel<<<EB, 256>>>(dst, nE);

    scan_block_kernel<<<SCAN_NB, SCAN_B>>>();
    scan_tops_kernel<<<1, 128>>>();
    scan_add_kernel<<<SCAN_NB, SCAN_B>>>();

    bin_kernel<<<EB, 256>>>(src, dst, ew, nE);

    // gather: one warp per node (fp16 feature reads)
    gather_kernel<<<(NN * 32 + 255) / 256, 256>>>();

    // tf32 GEMM
    int smem = (2 * D * LDS_PAD + D) * (int)sizeof(float);
    cudaFuncSetAttribute(gemm_tf32_kernel,
                         cudaFuncAttributeMaxDynamicSharedMemorySize, smem);
    gemm_tf32_kernel<<<(NN + 127) / 128, 256, smem>>>(W, b, y);
}